// round 3
// baseline (speedup 1.0000x reference)
#include <cuda_runtime.h>
#include <cuda_bf16.h>

// Problem constants (fixed shapes from reference)
#define DIMC  1024
#define NH    16
#define HD    64
#define SEQ   2048
#define BATCH 2
#define SCALE_Q 0.125f   // HEAD_DIM^-0.5 = 64^-0.5

// Scratch (device globals — no runtime allocation allowed)
__device__ float g_Q[BATCH * NH * SEQ * HD];   // [B,H,N,D], pre-scaled by SCALE_Q
__device__ float g_K[BATCH * NH * SEQ * HD];   // [B,H,N,D]
__device__ float g_V[BATCH * NH * SEQ * HD];   // [B,H,N,D]
__device__ float g_O[BATCH * SEQ * DIMC];      // [B,N,C] attention out (pre-transposed)

// ============================================================================
// GEMM (TN): C[m,n] = sum_k A[m,k] * B[n,k]
// A: [M,K] row-major, B: [N,K] row-major. M,N multiples of 128; K multiple of 16.
// Tile 128x128x16, 256 threads, 8x8 per-thread micro-tile.
// mode 0: QKV epilogue -> scatter into g_Q (scaled), g_K, g_V  ([B,H,N,D])
// mode 1: proj epilogue -> Out[m*N+n] = acc + bias[n]
// ============================================================================
__global__ __launch_bounds__(256) void gemm_tn_kernel(
    const float* __restrict__ A, const float* __restrict__ B,
    int M, int N, int K, int mode,
    float* __restrict__ Qb, float* __restrict__ Kb, float* __restrict__ Vb,
    const float* __restrict__ bias, float* __restrict__ Out)
{
    __shared__ float As[16][132];   // [k][m], padded to avoid bank conflicts
    __shared__ float Bs[16][132];   // [k][n]

    const int tid  = threadIdx.x;
    const int m0   = blockIdx.y * 128;
    const int n0   = blockIdx.x * 128;
    const int warp = tid >> 5;
    const int lane = tid & 31;
    // warps 4x2 (MxN), each warp 32x64; lanes 4x8, each thread 8x8
    const int tm = ((warp >> 1) << 5) + ((lane >> 3) << 3);
    const int tn = ((warp & 1) << 6) + ((lane & 7) << 3);
    // global->shared load mapping: 2 float4 per operand per thread
    const int lrow = tid >> 2;          // 0..63
    const int lk4  = (tid & 3) << 2;    // 0,4,8,12

    float acc[8][8];
    #pragma unroll
    for (int i = 0; i < 8; i++)
        #pragma unroll
        for (int j = 0; j < 8; j++) acc[i][j] = 0.f;

    const float* Ap0 = A + (m0 + lrow) * K + lk4;
    const float* Ap1 = A + (m0 + lrow + 64) * K + lk4;
    const float* Bp0 = B + (n0 + lrow) * K + lk4;
    const float* Bp1 = B + (n0 + lrow + 64) * K + lk4;

    for (int kt = 0; kt < K; kt += 16) {
        float4 a0 = *(const float4*)(Ap0 + kt);
        float4 a1 = *(const float4*)(Ap1 + kt);
        float4 b0 = *(const float4*)(Bp0 + kt);
        float4 b1 = *(const float4*)(Bp1 + kt);

        As[lk4 + 0][lrow] = a0.x; As[lk4 + 1][lrow] = a0.y;
        As[lk4 + 2][lrow] = a0.z; As[lk4 + 3][lrow] = a0.w;
        As[lk4 + 0][lrow + 64] = a1.x; As[lk4 + 1][lrow + 64] = a1.y;
        As[lk4 + 2][lrow + 64] = a1.z; As[lk4 + 3][lrow + 64] = a1.w;
        Bs[lk4 + 0][lrow] = b0.x; Bs[lk4 + 1][lrow] = b0.y;
        Bs[lk4 + 2][lrow] = b0.z; Bs[lk4 + 3][lrow] = b0.w;
        Bs[lk4 + 0][lrow + 64] = b1.x; Bs[lk4 + 1][lrow + 64] = b1.y;
        Bs[lk4 + 2][lrow + 64] = b1.z; Bs[lk4 + 3][lrow + 64] = b1.w;
        __syncthreads();

        #pragma unroll
        for (int k = 0; k < 16; k++) {
            float ar[8], br[8];
            *(float4*)&ar[0] = *(const float4*)&As[k][tm];
            *(float4*)&ar[4] = *(const float4*)&As[k][tm + 4];
            *(float4*)&br[0] = *(const float4*)&Bs[k][tn];
            *(float4*)&br[4] = *(const float4*)&Bs[k][tn + 4];
            #pragma unroll
            for (int i = 0; i < 8; i++)
                #pragma unroll
                for (int j = 0; j < 8; j++)
                    acc[i][j] += ar[i] * br[j];
        }
        __syncthreads();
    }

    if (mode == 0) {
        // o = t*1024 + h*64 + d  (qkv reshape [B,N,3,H,D]); dst [B,H,N,D]
        #pragma unroll
        for (int i = 0; i < 8; i++) {
            int m = m0 + tm + i;
            int b = m >> 11, n = m & 2047;
            #pragma unroll
            for (int j = 0; j < 8; j++) {
                int o = n0 + tn + j;
                int t = o >> 10;
                int h = (o >> 6) & 15;
                int d = o & 63;
                int dst = (((b << 4) + h) * SEQ + n) * HD + d;
                float v = acc[i][j];
                if (t == 0)      Qb[dst] = v * SCALE_Q;
                else if (t == 1) Kb[dst] = v;
                else             Vb[dst] = v;
            }
        }
    } else {
        #pragma unroll
        for (int i = 0; i < 8; i++) {
            int m = m0 + tm + i;
            #pragma unroll
            for (int j = 0; j < 8; j++) {
                int n = n0 + tn + j;
                Out[m * N + n] = acc[i][j] + bias[n];
            }
        }
    }
}

// ============================================================================
// Flash-style attention, fp32. One CTA = 64 query rows of one (b,h).
// 256 threads: thread t -> row r = t>>2, column-group cg = t&3.
// QK: thread owns S[r][c] for c = 4j+cg (j=0..15)  (interleaved -> conflict-free)
// PV: thread owns O[r][dv] for dv = cg*4 + 16k + e  (k=0..3, e=0..3)
// ============================================================================
#define ALD 68                      // padded smem row (floats)
#define ATTN_SMEM (4 * 64 * ALD * 4)

__global__ __launch_bounds__(256) void attn_kernel(
    const float* __restrict__ Qb, const float* __restrict__ Kb,
    const float* __restrict__ Vb, float* __restrict__ Ob)
{
    extern __shared__ float sm[];
    float* Qs = sm;                 // [64][ALD]
    float* Ks = Qs + 64 * ALD;
    float* Vs = Ks + 64 * ALD;
    float* Ss = Vs + 64 * ALD;

    const int tid = threadIdx.x;
    const int bh  = blockIdx.y;                 // 0..31  (b*16+h)
    const int q0  = blockIdx.x * 64;
    const float* Qp = Qb + (size_t)bh * SEQ * HD;
    const float* Kp = Kb + (size_t)bh * SEQ * HD;
    const float* Vp = Vb + (size_t)bh * SEQ * HD;

    const int r  = tid >> 2;    // 0..63
    const int cg = tid & 3;     // 0..3

    // Load Q tile (64x64) into smem
    #pragma unroll
    for (int i = 0; i < 4; i++) {
        int f = tid + i * 256;              // 0..1023
        int row = f >> 4;
        int d4  = (f & 15) << 2;
        *(float4*)&Qs[row * ALD + d4] = *(const float4*)&Qp[(q0 + row) * HD + d4];
    }

    float m_run = -1e30f, l_run = 0.f;
    float o_acc[4][4];
    #pragma unroll
    for (int k = 0; k < 4; k++)
        #pragma unroll
        for (int e = 0; e < 4; e++) o_acc[k][e] = 0.f;

    for (int c0 = 0; c0 < SEQ; c0 += 64) {
        __syncthreads();   // previous PV done with Ss/Vs; Q visible on first iter
        #pragma unroll
        for (int i = 0; i < 4; i++) {
            int f = tid + i * 256;
            int row = f >> 4;
            int d4  = (f & 15) << 2;
            *(float4*)&Ks[row * ALD + d4] = *(const float4*)&Kp[(c0 + row) * HD + d4];
            *(float4*)&Vs[row * ALD + d4] = *(const float4*)&Vp[(c0 + row) * HD + d4];
        }
        __syncthreads();

        // ---- S = Q K^T for this thread's 16 columns ----
        float s[16];
        #pragma unroll
        for (int j = 0; j < 16; j++) s[j] = 0.f;
        const float* Kbase = Ks + cg * ALD;   // c = 4j+cg
        for (int d = 0; d < HD; d += 4) {
            float4 q4 = *(const float4*)&Qs[r * ALD + d];
            #pragma unroll
            for (int j = 0; j < 16; j++) {
                float4 k4 = *(const float4*)&Kbase[(j << 2) * ALD + d];
                s[j] += q4.x * k4.x + q4.y * k4.y + q4.z * k4.z + q4.w * k4.w;
            }
        }

        // ---- online softmax (row groups of 4 lanes) ----
        float mt = s[0];
        #pragma unroll
        for (int j = 1; j < 16; j++) mt = fmaxf(mt, s[j]);
        mt = fmaxf(mt, __shfl_xor_sync(0xffffffffu, mt, 1, 4));
        mt = fmaxf(mt, __shfl_xor_sync(0xffffffffu, mt, 2, 4));
        float m_new = fmaxf(m_run, mt);
        float alpha = __expf(m_run - m_new);
        float lsum = 0.f;
        #pragma unroll
        for (int j = 0; j < 16; j++) {
            s[j] = __expf(s[j] - m_new);
            lsum += s[j];
        }
        lsum += __shfl_xor_sync(0xffffffffu, lsum, 1, 4);
        lsum += __shfl_xor_sync(0xffffffffu, lsum, 2, 4);
        l_run = l_run * alpha + lsum;
        m_run = m_new;
        #pragma unroll
        for (int k = 0; k < 4; k++)
            #pragma unroll
            for (int e = 0; e < 4; e++) o_acc[k][e] *= alpha;

        // publish P
        #pragma unroll
        for (int j = 0; j < 16; j++) Ss[r * ALD + (j << 2) + cg] = s[j];
        __syncthreads();

        // ---- O += P V ----
        const float* Vbase = Vs + (cg << 2);
        for (int c = 0; c < 64; c += 4) {
            float4 p4 = *(const float4*)&Ss[r * ALD + c];
            #pragma unroll
            for (int cc = 0; cc < 4; cc++) {
                float p = (cc == 0) ? p4.x : (cc == 1) ? p4.y : (cc == 2) ? p4.z : p4.w;
                const float* vr = Vbase + (c + cc) * ALD;
                #pragma unroll
                for (int k = 0; k < 4; k++) {
                    float4 v4 = *(const float4*)&vr[k << 4];
                    o_acc[k][0] += p * v4.x;
                    o_acc[k][1] += p * v4.y;
                    o_acc[k][2] += p * v4.z;
                    o_acc[k][3] += p * v4.w;
                }
            }
        }
    }

    // ---- finalize & write O in [B,N,H*D] layout (pre-transposed for proj) ----
    float inv = 1.f / l_run;
    int b = bh >> 4, h = bh & 15;
    int gr = q0 + r;
    float* dst = Ob + ((size_t)(b * SEQ + gr)) * DIMC + h * HD;
    #pragma unroll
    for (int k = 0; k < 4; k++) {
        float4 v;
        v.x = o_acc[k][0] * inv;
        v.y = o_acc[k][1] * inv;
        v.z = o_acc[k][2] * inv;
        v.w = o_acc[k][3] * inv;
        *(float4*)&dst[(cg << 2) + (k << 4)] = v;
    }
}

// ============================================================================
// Launcher
// ============================================================================
extern "C" void kernel_launch(void* const* d_in, const int* in_sizes, int n_in,
                              void* d_out, int out_size)
{
    const float* x     = (const float*)d_in[0];   // [2,2048,1024]
    const float* Wqkv  = (const float*)d_in[1];   // [3072,1024]
    const float* Wproj = (const float*)d_in[2];   // [1024,1024]
    const float* bproj = (const float*)d_in[3];   // [1024]
    float* out = (float*)d_out;                   // [2,2048,1024]

    float *Qb, *Kb, *Vb, *Ob;
    cudaGetSymbolAddress((void**)&Qb, g_Q);
    cudaGetSymbolAddress((void**)&Kb, g_K);
    cudaGetSymbolAddress((void**)&Vb, g_V);
    cudaGetSymbolAddress((void**)&Ob, g_O);

    cudaFuncSetAttribute(attn_kernel,
                         cudaFuncAttributeMaxDynamicSharedMemorySize, ATTN_SMEM);

    const int M = BATCH * SEQ;   // 4096

    // 1) QKV projection: [4096,1024] x [3072,1024]^T -> scatter Q/K/V
    dim3 g1(3 * DIMC / 128, M / 128);   // (24, 32)
    gemm_tn_kernel<<<g1, 256>>>(x, Wqkv, M, 3 * DIMC, DIMC, 0,
                                Qb, Kb, Vb, nullptr, nullptr);

    // 2) attention
    dim3 g2(SEQ / 64, BATCH * NH);      // (32, 32)
    attn_kernel<<<g2, 256, ATTN_SMEM>>>(Qb, Kb, Vb, Ob);

    // 3) output projection: [4096,1024] x [1024,1024]^T + bias -> out
    dim3 g3(DIMC / 128, M / 128);       // (8, 32)
    gemm_tn_kernel<<<g3, 256>>>(Ob, Wproj, M, DIMC, DIMC, 1,
                                nullptr, nullptr, nullptr, bproj, out);
}

// round 5
// speedup vs baseline: 2.1390x; 2.1390x over previous
#include <cuda_runtime.h>
#include <cuda_bf16.h>
#include <cstdint>

// ---------------- problem constants ----------------
#define DIMC  1024
#define NH    16
#define HD    64
#define SEQ   2048
#define BATCH 2
#define GK    1024
#define SCALE_Q 0.125f

// scratch (device globals; no runtime allocation)
__device__ float g_Q[BATCH * NH * SEQ * HD];   // [B,H,N,D], pre-scaled
__device__ float g_K[BATCH * NH * SEQ * HD];
__device__ float g_V[BATCH * NH * SEQ * HD];
__device__ float g_O[BATCH * SEQ * DIMC];      // [B,N,C]

__device__ __forceinline__ uint32_t f2tf32(float x) {
    uint32_t r;
    asm("cvt.rna.tf32.f32 %0, %1;" : "=r"(r) : "f"(x));
    return r;
}

__device__ __forceinline__ void mma_tf32(float* c, const uint32_t* a, const uint32_t* b) {
    asm volatile(
        "mma.sync.aligned.m16n8k8.row.col.f32.tf32.tf32.f32 "
        "{%0,%1,%2,%3}, {%4,%5,%6,%7}, {%8,%9}, {%0,%1,%2,%3};"
        : "+f"(c[0]), "+f"(c[1]), "+f"(c[2]), "+f"(c[3])
        : "r"(a[0]), "r"(a[1]), "r"(a[2]), "r"(a[3]), "r"(b[0]), "r"(b[1]));
}

// ============================================================================
// TN GEMM via mma.sync tf32: C[m,n] = sum_k A[m,k] * B[n,k]
// CTA tile 128x128, K-chunk 32, 256 threads = 8 warps (2 M x 4 N), warp 64x32.
// smem: double-buffered A/B tiles, stride 36 floats (conflict-free frag loads).
// mode 0: QKV scatter epilogue (Q scaled); mode 1: proj + bias epilogue.
// ============================================================================
#define GLD 36                         // smem row stride (floats)
#define GEMM_BUF (2 * 128 * GLD)       // floats per buffer (A + B)
#define GEMM_SMEM (2 * GEMM_BUF * 4)   // bytes (double buffered)

__global__ __launch_bounds__(256) void gemm_mma_kernel(
    const float* __restrict__ A, const float* __restrict__ B, int mode,
    float* __restrict__ Qb, float* __restrict__ Kb, float* __restrict__ Vb,
    const float* __restrict__ bias, float* __restrict__ Out)
{
    extern __shared__ float sm[];
    const int tid = threadIdx.x, wid = tid >> 5, lane = tid & 31;
    const int n0 = blockIdx.x * 128, m0 = blockIdx.y * 128;
    const int wm = wid >> 2;           // 0..1 -> m offset 64*wm
    const int wn = wid & 3;            // 0..3 -> n offset 32*wn
    const int lr = lane >> 2, lc = lane & 3;

    // global load mapping: 4 float4 per matrix per thread per chunk
    const int lrow = tid >> 3;         // 0..31 (+ i*32)
    const int lc4  = (tid & 7) << 2;   // 0..28
    const float* Ag = A + (size_t)m0 * GK;
    const float* Bg = B + (size_t)n0 * GK;

    float acc[4][4][4];
    #pragma unroll
    for (int mt = 0; mt < 4; mt++)
        #pragma unroll
        for (int nt = 0; nt < 4; nt++)
            #pragma unroll
            for (int j = 0; j < 4; j++) acc[mt][nt][j] = 0.f;

    float4 apf[4], bpf[4];
    // prologue: load chunk 0
    #pragma unroll
    for (int i = 0; i < 4; i++) {
        int row = lrow + i * 32;
        apf[i] = *(const float4*)(Ag + (size_t)row * GK + lc4);
        bpf[i] = *(const float4*)(Bg + (size_t)row * GK + lc4);
    }
    {   // store chunk 0 -> buf 0
        float* As = sm;
        float* Bs = sm + 128 * GLD;
        #pragma unroll
        for (int i = 0; i < 4; i++) {
            int row = lrow + i * 32;
            float4 a = apf[i], b = bpf[i];
            uint4 at, bt;
            at.x = f2tf32(a.x); at.y = f2tf32(a.y); at.z = f2tf32(a.z); at.w = f2tf32(a.w);
            bt.x = f2tf32(b.x); bt.y = f2tf32(b.y); bt.z = f2tf32(b.z); bt.w = f2tf32(b.w);
            *(uint4*)&As[row * GLD + lc4] = at;
            *(uint4*)&Bs[row * GLD + lc4] = bt;
        }
    }
    __syncthreads();

    const int NCHUNK = GK / 32;
    for (int kt = 0; kt < NCHUNK; kt++) {
        // prefetch next chunk to regs (overlaps with compute)
        if (kt + 1 < NCHUNK) {
            #pragma unroll
            for (int i = 0; i < 4; i++) {
                int row = lrow + i * 32;
                apf[i] = *(const float4*)(Ag + (size_t)row * GK + (kt + 1) * 32 + lc4);
                bpf[i] = *(const float4*)(Bg + (size_t)row * GK + (kt + 1) * 32 + lc4);
            }
        }
        // compute current buffer
        const uint32_t* As = (const uint32_t*)(sm + (kt & 1) * GEMM_BUF);
        const uint32_t* Bs = As + 128 * GLD;
        #pragma unroll
        for (int ks = 0; ks < 4; ks++) {
            uint32_t afr[4][4], bfr[4][2];
            #pragma unroll
            for (int mt = 0; mt < 4; mt++) {
                int base = (wm * 64 + mt * 16 + lr) * GLD + ks * 8 + lc;
                afr[mt][0] = As[base];
                afr[mt][1] = As[base + 8 * GLD];
                afr[mt][2] = As[base + 4];
                afr[mt][3] = As[base + 8 * GLD + 4];
            }
            #pragma unroll
            for (int nt = 0; nt < 4; nt++) {
                int base = (wn * 32 + nt * 8 + lr) * GLD + ks * 8 + lc;
                bfr[nt][0] = Bs[base];
                bfr[nt][1] = Bs[base + 4];
            }
            #pragma unroll
            for (int mt = 0; mt < 4; mt++)
                #pragma unroll
                for (int nt = 0; nt < 4; nt++)
                    mma_tf32(acc[mt][nt], afr[mt], bfr[nt]);
        }
        __syncthreads();
        if (kt + 1 < NCHUNK) {
            float* Asw = sm + ((kt + 1) & 1) * GEMM_BUF;
            float* Bsw = Asw + 128 * GLD;
            #pragma unroll
            for (int i = 0; i < 4; i++) {
                int row = lrow + i * 32;
                float4 a = apf[i], b = bpf[i];
                uint4 at, bt;
                at.x = f2tf32(a.x); at.y = f2tf32(a.y); at.z = f2tf32(a.z); at.w = f2tf32(a.w);
                bt.x = f2tf32(b.x); bt.y = f2tf32(b.y); bt.z = f2tf32(b.z); bt.w = f2tf32(b.w);
                *(uint4*)&Asw[row * GLD + lc4] = at;
                *(uint4*)&Bsw[row * GLD + lc4] = bt;
            }
            __syncthreads();
        }
    }

    // ---- epilogue: fragment -> global (float2 per pair) ----
    #pragma unroll
    for (int mt = 0; mt < 4; mt++) {
        #pragma unroll
        for (int nt = 0; nt < 4; nt++) {
            #pragma unroll
            for (int half = 0; half < 2; half++) {
                int row = m0 + wm * 64 + mt * 16 + lr + half * 8;
                int col = n0 + wn * 32 + nt * 8 + lc * 2;
                float2 v;
                v.x = acc[mt][nt][half * 2 + 0];
                v.y = acc[mt][nt][half * 2 + 1];
                if (mode == 0) {
                    int b = row >> 11, n = row & 2047;
                    int t = col >> 10, h = (col >> 6) & 15, d = col & 63;
                    size_t dst = ((size_t)((b << 4) + h) * SEQ + n) * HD + d;
                    if (t == 0) {
                        v.x *= SCALE_Q; v.y *= SCALE_Q;
                        *(float2*)(Qb + dst) = v;
                    } else if (t == 1) *(float2*)(Kb + dst) = v;
                    else               *(float2*)(Vb + dst) = v;
                } else {
                    float2 bb = *(const float2*)(bias + col);
                    v.x += bb.x; v.y += bb.y;
                    *(float2*)(Out + (size_t)row * DIMC + col) = v;
                }
            }
        }
    }
}

// ============================================================================
// Flash attention, fp32 SIMT, 2 q-rows per thread (halves K/V smem traffic).
// CTA = 64 q-rows of one (b,h); 128 threads: r = tid>>2 in [0,32), rows r & r+32;
// cg = tid&3, cols 4j+cg.
// ============================================================================
#define ALD 68
#define ATTN_SMEM (4 * 64 * ALD * 4)

__global__ __launch_bounds__(128) void attn_kernel(
    const float* __restrict__ Qb, const float* __restrict__ Kb,
    const float* __restrict__ Vb, float* __restrict__ Ob)
{
    extern __shared__ float smf[];
    float* Qs = smf;
    float* Ks = Qs + 64 * ALD;
    float* Vs = Ks + 64 * ALD;
    float* Ss = Vs + 64 * ALD;

    const int tid = threadIdx.x;
    const int bh  = blockIdx.y;
    const int q0  = blockIdx.x * 64;
    const float* Qp = Qb + (size_t)bh * SEQ * HD;
    const float* Kp = Kb + (size_t)bh * SEQ * HD;
    const float* Vp = Vb + (size_t)bh * SEQ * HD;

    const int r  = tid >> 2;    // 0..31
    const int cg = tid & 3;

    #pragma unroll
    for (int i = 0; i < 8; i++) {
        int f = tid + i * 128;
        int row = f >> 4, d4 = (f & 15) << 2;
        *(float4*)&Qs[row * ALD + d4] = *(const float4*)&Qp[(size_t)(q0 + row) * HD + d4];
    }

    float m_run[2] = { -1e30f, -1e30f };
    float l_run[2] = { 0.f, 0.f };
    float o_acc[2][4][4];
    #pragma unroll
    for (int x = 0; x < 2; x++)
        #pragma unroll
        for (int k = 0; k < 4; k++)
            #pragma unroll
            for (int e = 0; e < 4; e++) o_acc[x][k][e] = 0.f;

    for (int c0 = 0; c0 < SEQ; c0 += 64) {
        __syncthreads();
        #pragma unroll
        for (int i = 0; i < 8; i++) {
            int f = tid + i * 128;
            int row = f >> 4, d4 = (f & 15) << 2;
            *(float4*)&Ks[row * ALD + d4] = *(const float4*)&Kp[(size_t)(c0 + row) * HD + d4];
            *(float4*)&Vs[row * ALD + d4] = *(const float4*)&Vp[(size_t)(c0 + row) * HD + d4];
        }
        __syncthreads();

        // ---- S = Q K^T : 2 rows x 16 cols per thread ----
        float s0[16], s1[16];
        #pragma unroll
        for (int j = 0; j < 16; j++) { s0[j] = 0.f; s1[j] = 0.f; }
        const float* Kbase = Ks + cg * ALD;
        for (int d = 0; d < HD; d += 4) {
            float4 qa = *(const float4*)&Qs[r * ALD + d];
            float4 qb = *(const float4*)&Qs[(r + 32) * ALD + d];
            #pragma unroll
            for (int j = 0; j < 16; j++) {
                float4 k4 = *(const float4*)&Kbase[(j << 2) * ALD + d];
                s0[j] += qa.x * k4.x + qa.y * k4.y + qa.z * k4.z + qa.w * k4.w;
                s1[j] += qb.x * k4.x + qb.y * k4.y + qb.z * k4.z + qb.w * k4.w;
            }
        }

        // ---- online softmax (lane groups of 4) ----
        #pragma unroll
        for (int x = 0; x < 2; x++) {
            float* s = (x == 0) ? s0 : s1;
            float mt = s[0];
            #pragma unroll
            for (int j = 1; j < 16; j++) mt = fmaxf(mt, s[j]);
            mt = fmaxf(mt, __shfl_xor_sync(0xffffffffu, mt, 1, 4));
            mt = fmaxf(mt, __shfl_xor_sync(0xffffffffu, mt, 2, 4));
            float m_new = fmaxf(m_run[x], mt);
            float alpha = __expf(m_run[x] - m_new);
            float lsum = 0.f;
            #pragma unroll
            for (int j = 0; j < 16; j++) {
                s[j] = __expf(s[j] - m_new);
                lsum += s[j];
            }
            lsum += __shfl_xor_sync(0xffffffffu, lsum, 1, 4);
            lsum += __shfl_xor_sync(0xffffffffu, lsum, 2, 4);
            l_run[x] = l_run[x] * alpha + lsum;
            m_run[x] = m_new;
            #pragma unroll
            for (int k = 0; k < 4; k++)
                #pragma unroll
                for (int e = 0; e < 4; e++) o_acc[x][k][e] *= alpha;
        }

        #pragma unroll
        for (int j = 0; j < 16; j++) {
            Ss[r * ALD + (j << 2) + cg]        = s0[j];
            Ss[(r + 32) * ALD + (j << 2) + cg] = s1[j];
        }
        __syncthreads();

        // ---- O += P V : V vectors amortized across 2 rows ----
        const float* Vbase = Vs + (cg << 2);
        for (int c = 0; c < 64; c += 4) {
            float4 pa = *(const float4*)&Ss[r * ALD + c];
            float4 pb = *(const float4*)&Ss[(r + 32) * ALD + c];
            #pragma unroll
            for (int cc = 0; cc < 4; cc++) {
                float fa = (cc == 0) ? pa.x : (cc == 1) ? pa.y : (cc == 2) ? pa.z : pa.w;
                float fb = (cc == 0) ? pb.x : (cc == 1) ? pb.y : (cc == 2) ? pb.z : pb.w;
                const float* vr = Vbase + (c + cc) * ALD;
                #pragma unroll
                for (int k = 0; k < 4; k++) {
                    float4 v4 = *(const float4*)&vr[k << 4];
                    o_acc[0][k][0] += fa * v4.x; o_acc[0][k][1] += fa * v4.y;
                    o_acc[0][k][2] += fa * v4.z; o_acc[0][k][3] += fa * v4.w;
                    o_acc[1][k][0] += fb * v4.x; o_acc[1][k][1] += fb * v4.y;
                    o_acc[1][k][2] += fb * v4.z; o_acc[1][k][3] += fb * v4.w;
                }
            }
        }
    }

    const int b = bh >> 4, h = bh & 15;
    #pragma unroll
    for (int x = 0; x < 2; x++) {
        float inv = 1.f / l_run[x];
        int gr = q0 + r + x * 32;
        float* dst = Ob + ((size_t)(b * SEQ + gr)) * DIMC + h * HD;
        #pragma unroll
        for (int k = 0; k < 4; k++) {
            float4 v;
            v.x = o_acc[x][k][0] * inv;
            v.y = o_acc[x][k][1] * inv;
            v.z = o_acc[x][k][2] * inv;
            v.w = o_acc[x][k][3] * inv;
            *(float4*)&dst[(cg << 2) + (k << 4)] = v;
        }
    }
}

// ============================================================================
// Launcher
// ============================================================================
extern "C" void kernel_launch(void* const* d_in, const int* in_sizes, int n_in,
                              void* d_out, int out_size)
{
    const float* x     = (const float*)d_in[0];   // [2,2048,1024]
    const float* Wqkv  = (const float*)d_in[1];   // [3072,1024]
    const float* Wproj = (const float*)d_in[2];   // [1024,1024]
    const float* bproj = (const float*)d_in[3];   // [1024]
    float* out = (float*)d_out;

    float *Qb, *Kb, *Vb, *Ob;
    cudaGetSymbolAddress((void**)&Qb, g_Q);
    cudaGetSymbolAddress((void**)&Kb, g_K);
    cudaGetSymbolAddress((void**)&Vb, g_V);
    cudaGetSymbolAddress((void**)&Ob, g_O);

    cudaFuncSetAttribute(gemm_mma_kernel,
                         cudaFuncAttributeMaxDynamicSharedMemorySize, GEMM_SMEM);
    cudaFuncSetAttribute(attn_kernel,
                         cudaFuncAttributeMaxDynamicSharedMemorySize, ATTN_SMEM);

    // 1) QKV projection (mma.sync tf32) with Q/K/V scatter
    dim3 g1(3 * DIMC / 128, (BATCH * SEQ) / 128);   // (24, 32)
    gemm_mma_kernel<<<g1, 256, GEMM_SMEM>>>(x, Wqkv, 0, Qb, Kb, Vb, nullptr, nullptr);

    // 2) attention (fp32 SIMT, 2 rows/thread)
    dim3 g2(SEQ / 64, BATCH * NH);                  // (32, 32)
    attn_kernel<<<g2, 128, ATTN_SMEM>>>(Qb, Kb, Vb, Ob);

    // 3) output projection (mma.sync tf32) + bias
    dim3 g3(DIMC / 128, (BATCH * SEQ) / 128);       // (8, 32)
    gemm_mma_kernel<<<g3, 256, GEMM_SMEM>>>(Ob, Wproj, 1, nullptr, nullptr, nullptr,
                                            bproj, out);
}

// round 7
// speedup vs baseline: 5.3696x; 2.5103x over previous
#include <cuda_runtime.h>
#include <cuda_bf16.h>
#include <cstdint>

// ---------------- problem constants ----------------
#define DIMC  1024
#define NH    16
#define HD    64
#define SEQ   2048
#define BATCH 2
#define GK    1024
#define SCALE_Q 0.125f

// scratch (device globals; no runtime allocation)
__device__ float g_Q[BATCH * NH * SEQ * HD];   // [B,H,N,D], pre-scaled
__device__ float g_K[BATCH * NH * SEQ * HD];
__device__ float g_V[BATCH * NH * SEQ * HD];
__device__ float g_O[BATCH * SEQ * DIMC];      // [B,N,C]

__device__ __forceinline__ uint32_t f2tf32(float x) {
    uint32_t r;
    asm("cvt.rna.tf32.f32 %0, %1;" : "=r"(r) : "f"(x));
    return r;
}

__device__ __forceinline__ void mma_tf32(float* c, const uint32_t* a, const uint32_t* b) {
    asm volatile(
        "mma.sync.aligned.m16n8k8.row.col.f32.tf32.tf32.f32 "
        "{%0,%1,%2,%3}, {%4,%5,%6,%7}, {%8,%9}, {%0,%1,%2,%3};"
        : "+f"(c[0]), "+f"(c[1]), "+f"(c[2]), "+f"(c[3])
        : "r"(a[0]), "r"(a[1]), "r"(a[2]), "r"(a[3]), "r"(b[0]), "r"(b[1]));
}

// ============================================================================
// TN GEMM via mma.sync tf32 (validated R5): C[m,n] = sum_k A[m,k] * B[n,k]
// CTA tile 128x128, K-chunk 32, 256 threads = 8 warps (2 M x 4 N), warp 64x32.
// ============================================================================
#define GLD 36
#define GEMM_BUF (2 * 128 * GLD)
#define GEMM_SMEM (2 * GEMM_BUF * 4)

__global__ __launch_bounds__(256) void gemm_mma_kernel(
    const float* __restrict__ A, const float* __restrict__ B, int mode,
    float* __restrict__ Qb, float* __restrict__ Kb, float* __restrict__ Vb,
    const float* __restrict__ bias, float* __restrict__ Out)
{
    extern __shared__ float sm[];
    const int tid = threadIdx.x, wid = tid >> 5, lane = tid & 31;
    const int n0 = blockIdx.x * 128, m0 = blockIdx.y * 128;
    const int wm = wid >> 2;
    const int wn = wid & 3;
    const int lr = lane >> 2, lc = lane & 3;

    const int lrow = tid >> 3;
    const int lc4  = (tid & 7) << 2;
    const float* Ag = A + (size_t)m0 * GK;
    const float* Bg = B + (size_t)n0 * GK;

    float acc[4][4][4];
    #pragma unroll
    for (int mt = 0; mt < 4; mt++)
        #pragma unroll
        for (int nt = 0; nt < 4; nt++)
            #pragma unroll
            for (int j = 0; j < 4; j++) acc[mt][nt][j] = 0.f;

    float4 apf[4], bpf[4];
    #pragma unroll
    for (int i = 0; i < 4; i++) {
        int row = lrow + i * 32;
        apf[i] = *(const float4*)(Ag + (size_t)row * GK + lc4);
        bpf[i] = *(const float4*)(Bg + (size_t)row * GK + lc4);
    }
    {
        float* As = sm;
        float* Bs = sm + 128 * GLD;
        #pragma unroll
        for (int i = 0; i < 4; i++) {
            int row = lrow + i * 32;
            float4 a = apf[i], b = bpf[i];
            uint4 at, bt;
            at.x = f2tf32(a.x); at.y = f2tf32(a.y); at.z = f2tf32(a.z); at.w = f2tf32(a.w);
            bt.x = f2tf32(b.x); bt.y = f2tf32(b.y); bt.z = f2tf32(b.z); bt.w = f2tf32(b.w);
            *(uint4*)&As[row * GLD + lc4] = at;
            *(uint4*)&Bs[row * GLD + lc4] = bt;
        }
    }
    __syncthreads();

    const int NCHUNK = GK / 32;
    for (int kt = 0; kt < NCHUNK; kt++) {
        if (kt + 1 < NCHUNK) {
            #pragma unroll
            for (int i = 0; i < 4; i++) {
                int row = lrow + i * 32;
                apf[i] = *(const float4*)(Ag + (size_t)row * GK + (kt + 1) * 32 + lc4);
                bpf[i] = *(const float4*)(Bg + (size_t)row * GK + (kt + 1) * 32 + lc4);
            }
        }
        const uint32_t* As = (const uint32_t*)(sm + (kt & 1) * GEMM_BUF);
        const uint32_t* Bs = As + 128 * GLD;
        #pragma unroll
        for (int ks = 0; ks < 4; ks++) {
            uint32_t afr[4][4], bfr[4][2];
            #pragma unroll
            for (int mt = 0; mt < 4; mt++) {
                int base = (wm * 64 + mt * 16 + lr) * GLD + ks * 8 + lc;
                afr[mt][0] = As[base];
                afr[mt][1] = As[base + 8 * GLD];
                afr[mt][2] = As[base + 4];
                afr[mt][3] = As[base + 8 * GLD + 4];
            }
            #pragma unroll
            for (int nt = 0; nt < 4; nt++) {
                int base = (wn * 32 + nt * 8 + lr) * GLD + ks * 8 + lc;
                bfr[nt][0] = Bs[base];
                bfr[nt][1] = Bs[base + 4];
            }
            #pragma unroll
            for (int mt = 0; mt < 4; mt++)
                #pragma unroll
                for (int nt = 0; nt < 4; nt++)
                    mma_tf32(acc[mt][nt], afr[mt], bfr[nt]);
        }
        __syncthreads();
        if (kt + 1 < NCHUNK) {
            float* Asw = sm + ((kt + 1) & 1) * GEMM_BUF;
            float* Bsw = Asw + 128 * GLD;
            #pragma unroll
            for (int i = 0; i < 4; i++) {
                int row = lrow + i * 32;
                float4 a = apf[i], b = bpf[i];
                uint4 at, bt;
                at.x = f2tf32(a.x); at.y = f2tf32(a.y); at.z = f2tf32(a.z); at.w = f2tf32(a.w);
                bt.x = f2tf32(b.x); bt.y = f2tf32(b.y); bt.z = f2tf32(b.z); bt.w = f2tf32(b.w);
                *(uint4*)&Asw[row * GLD + lc4] = at;
                *(uint4*)&Bsw[row * GLD + lc4] = bt;
            }
            __syncthreads();
        }
    }

    #pragma unroll
    for (int mt = 0; mt < 4; mt++) {
        #pragma unroll
        for (int nt = 0; nt < 4; nt++) {
            #pragma unroll
            for (int half = 0; half < 2; half++) {
                int row = m0 + wm * 64 + mt * 16 + lr + half * 8;
                int col = n0 + wn * 32 + nt * 8 + lc * 2;
                float2 v;
                v.x = acc[mt][nt][half * 2 + 0];
                v.y = acc[mt][nt][half * 2 + 1];
                if (mode == 0) {
                    int b = row >> 11, n = row & 2047;
                    int t = col >> 10, h = (col >> 6) & 15, d = col & 63;
                    size_t dst = ((size_t)((b << 4) + h) * SEQ + n) * HD + d;
                    if (t == 0) {
                        v.x *= SCALE_Q; v.y *= SCALE_Q;
                        *(float2*)(Qb + dst) = v;
                    } else if (t == 1) *(float2*)(Kb + dst) = v;
                    else               *(float2*)(Vb + dst) = v;
                } else {
                    float2 bb = *(const float2*)(bias + col);
                    v.x += bb.x; v.y += bb.y;
                    *(float2*)(Out + (size_t)row * DIMC + col) = v;
                }
            }
        }
    }
}

// ============================================================================
// Flash attention via mma.sync tf32.
// CTA: 128 q-rows of one (b,h); 8 warps x 16 rows (full rows per warp ->
// softmax reductions stay within lane quads). KV tile 64. fp32 accumulate,
// fp32 online softmax; P staged tf32 in warp-private smem, PV accumulates
// straight into the O C-fragments.
// ============================================================================
#define QT 128
#define KT 64
#define KLD 68     // K smem stride -> S B-frag loads conflict-free (4*lr+lc)
#define VLD 72     // V smem stride -> PV B-frag loads conflict-free (8*lc+lr)
#define PLD 68     // P / Q-staging stride
#define AT_SMEM ((KT * KLD + KT * VLD + QT * PLD) * 4)

__global__ __launch_bounds__(256) void attn_mma_kernel(
    const float* __restrict__ Qb, const float* __restrict__ Kb,
    const float* __restrict__ Vb, float* __restrict__ Ob)
{
    extern __shared__ float smf[];
    float* Ks = smf;
    float* Vs = Ks + KT * KLD;
    float* Ps = Vs + KT * VLD;          // doubles as Q staging before the loop
    uint32_t* Ksu = (uint32_t*)Ks;
    uint32_t* Vsu = (uint32_t*)Vs;

    const int tid = threadIdx.x, wid = tid >> 5, lane = tid & 31;
    const int lr = lane >> 2, lc = lane & 3;
    const int bh = blockIdx.y;
    const int q0 = blockIdx.x * QT;
    const float* Qp = Qb + (size_t)bh * SEQ * HD;
    const float* Kp = Kb + (size_t)bh * SEQ * HD;
    const float* Vp = Vb + (size_t)bh * SEQ * HD;

    // ---- stage Q tile to smem (coalesced), build per-warp A fragments ----
    #pragma unroll
    for (int i = 0; i < 8; i++) {
        int f = tid + i * 256;              // 0..2047
        int row = f >> 4, d4 = (f & 15) << 2;
        *(float4*)&Ps[row * PLD + d4] = *(const float4*)&Qp[(size_t)(q0 + row) * HD + d4];
    }
    __syncthreads();

    uint32_t qf[8][4];
    {
        const float* Qw = Ps + (wid * 16) * PLD;
        #pragma unroll
        for (int kt = 0; kt < 8; kt++) {
            qf[kt][0] = f2tf32(Qw[lr * PLD + kt * 8 + lc]);
            qf[kt][1] = f2tf32(Qw[(lr + 8) * PLD + kt * 8 + lc]);
            qf[kt][2] = f2tf32(Qw[lr * PLD + kt * 8 + lc + 4]);
            qf[kt][3] = f2tf32(Qw[(lr + 8) * PLD + kt * 8 + lc + 4]);
        }
    }

    float m_run[2] = { -1e30f, -1e30f };
    float l_run[2] = { 0.f, 0.f };
    float oacc[8][4];
    #pragma unroll
    for (int nt = 0; nt < 8; nt++)
        #pragma unroll
        for (int j = 0; j < 4; j++) oacc[nt][j] = 0.f;

    uint32_t* Pwu = (uint32_t*)(Ps + (wid * 16) * PLD);

    for (int c0 = 0; c0 < SEQ; c0 += KT) {
        __syncthreads();    // prev iter done with Ks/Vs; Q-staging reads done
        // ---- fill K/V tiles (tf32 bits) ----
        #pragma unroll
        for (int i = 0; i < 4; i++) {
            int f = tid + i * 256;          // 0..1023
            int row = f >> 4, d4 = (f & 15) << 2;
            float4 k4 = *(const float4*)&Kp[(size_t)(c0 + row) * HD + d4];
            float4 v4 = *(const float4*)&Vp[(size_t)(c0 + row) * HD + d4];
            uint4 kt4, vt4;
            kt4.x = f2tf32(k4.x); kt4.y = f2tf32(k4.y); kt4.z = f2tf32(k4.z); kt4.w = f2tf32(k4.w);
            vt4.x = f2tf32(v4.x); vt4.y = f2tf32(v4.y); vt4.z = f2tf32(v4.z); vt4.w = f2tf32(v4.w);
            *(uint4*)&Ksu[row * KLD + d4] = kt4;
            *(uint4*)&Vsu[row * VLD + d4] = vt4;
        }
        __syncthreads();

        // ---- S = Q K^T (warp tile m16 x n64, k=64) ----
        float sacc[8][4];
        #pragma unroll
        for (int nt = 0; nt < 8; nt++)
            #pragma unroll
            for (int j = 0; j < 4; j++) sacc[nt][j] = 0.f;

        #pragma unroll
        for (int nt = 0; nt < 8; nt++) {
            int rbase = (nt * 8 + lr) * KLD + lc;
            #pragma unroll
            for (int kt = 0; kt < 8; kt++) {
                uint32_t b[2];
                b[0] = Ksu[rbase + kt * 8];
                b[1] = Ksu[rbase + kt * 8 + 4];
                mma_tf32(sacc[nt], qf[kt], b);
            }
        }

        // ---- fp32 online softmax; rows lr (x=0) and lr+8 (x=1) ----
        #pragma unroll
        for (int x = 0; x < 2; x++) {
            float mt = -1e30f;
            #pragma unroll
            for (int nt = 0; nt < 8; nt++)
                mt = fmaxf(mt, fmaxf(sacc[nt][2 * x], sacc[nt][2 * x + 1]));
            mt = fmaxf(mt, __shfl_xor_sync(0xffffffffu, mt, 1, 4));
            mt = fmaxf(mt, __shfl_xor_sync(0xffffffffu, mt, 2, 4));
            float m_new = fmaxf(m_run[x], mt);
            float alpha = __expf(m_run[x] - m_new);
            float lsum = 0.f;
            #pragma unroll
            for (int nt = 0; nt < 8; nt++) {
                float p0 = __expf(sacc[nt][2 * x]     - m_new);
                float p1 = __expf(sacc[nt][2 * x + 1] - m_new);
                sacc[nt][2 * x] = p0; sacc[nt][2 * x + 1] = p1;
                lsum += p0 + p1;
            }
            lsum += __shfl_xor_sync(0xffffffffu, lsum, 1, 4);
            lsum += __shfl_xor_sync(0xffffffffu, lsum, 2, 4);
            l_run[x] = l_run[x] * alpha + lsum;
            m_run[x] = m_new;
            #pragma unroll
            for (int nt = 0; nt < 8; nt++) {
                oacc[nt][2 * x]     *= alpha;
                oacc[nt][2 * x + 1] *= alpha;
            }
        }

        // ---- stage P (tf32) into warp-private smem strip ----
        #pragma unroll
        for (int nt = 0; nt < 8; nt++) {
            uint2 p0, p1;
            p0.x = f2tf32(sacc[nt][0]); p0.y = f2tf32(sacc[nt][1]);
            p1.x = f2tf32(sacc[nt][2]); p1.y = f2tf32(sacc[nt][3]);
            *(uint2*)&Pwu[lr * PLD + nt * 8 + 2 * lc]       = p0;
            *(uint2*)&Pwu[(lr + 8) * PLD + nt * 8 + 2 * lc] = p1;
        }
        __syncwarp();

        // ---- O += P V (warp tile m16 x n64, k=64 keys) ----
        #pragma unroll
        for (int kc = 0; kc < 8; kc++) {
            uint32_t a[4];
            a[0] = Pwu[lr * PLD + kc * 8 + lc];
            a[1] = Pwu[(lr + 8) * PLD + kc * 8 + lc];
            a[2] = Pwu[lr * PLD + kc * 8 + lc + 4];
            a[3] = Pwu[(lr + 8) * PLD + kc * 8 + lc + 4];
            int vbase0 = (kc * 8 + lc) * VLD + lr;
            int vbase1 = (kc * 8 + lc + 4) * VLD + lr;
            #pragma unroll
            for (int nt = 0; nt < 8; nt++) {
                uint32_t b[2];
                b[0] = Vsu[vbase0 + nt * 8];
                b[1] = Vsu[vbase1 + nt * 8];
                mma_tf32(oacc[nt], a, b);
            }
        }
    }

    // ---- finalize; write O in [B,N,C] layout ----
    const int b = bh >> 4, h = bh & 15;
    #pragma unroll
    for (int x = 0; x < 2; x++) {
        float inv = 1.f / l_run[x];
        int row = q0 + wid * 16 + lr + x * 8;
        float* dst = Ob + ((size_t)(b * SEQ + row)) * DIMC + h * HD;
        #pragma unroll
        for (int nt = 0; nt < 8; nt++) {
            float2 v;
            v.x = oacc[nt][2 * x]     * inv;
            v.y = oacc[nt][2 * x + 1] * inv;
            *(float2*)&dst[nt * 8 + 2 * lc] = v;
        }
    }
}

// ============================================================================
// Launcher
// ============================================================================
extern "C" void kernel_launch(void* const* d_in, const int* in_sizes, int n_in,
                              void* d_out, int out_size)
{
    const float* x     = (const float*)d_in[0];   // [2,2048,1024]
    const float* Wqkv  = (const float*)d_in[1];   // [3072,1024]
    const float* Wproj = (const float*)d_in[2];   // [1024,1024]
    const float* bproj = (const float*)d_in[3];   // [1024]
    float* out = (float*)d_out;

    float *Qb, *Kb, *Vb, *Ob;
    cudaGetSymbolAddress((void**)&Qb, g_Q);
    cudaGetSymbolAddress((void**)&Kb, g_K);
    cudaGetSymbolAddress((void**)&Vb, g_V);
    cudaGetSymbolAddress((void**)&Ob, g_O);

    cudaFuncSetAttribute(gemm_mma_kernel,
                         cudaFuncAttributeMaxDynamicSharedMemorySize, GEMM_SMEM);
    cudaFuncSetAttribute(attn_mma_kernel,
                         cudaFuncAttributeMaxDynamicSharedMemorySize, AT_SMEM);

    // 1) QKV projection (mma.sync tf32) with Q/K/V scatter
    dim3 g1(3 * DIMC / 128, (BATCH * SEQ) / 128);   // (24, 32)
    gemm_mma_kernel<<<g1, 256, GEMM_SMEM>>>(x, Wqkv, 0, Qb, Kb, Vb, nullptr, nullptr);

    // 2) flash attention (mma.sync tf32)
    dim3 g2(SEQ / QT, BATCH * NH);                  // (16, 32)
    attn_mma_kernel<<<g2, 256, AT_SMEM>>>(Qb, Kb, Vb, Ob);

    // 3) output projection (mma.sync tf32) + bias
    dim3 g3(DIMC / 128, (BATCH * SEQ) / 128);       // (8, 32)
    gemm_mma_kernel<<<g3, 256, GEMM_SMEM>>>(Ob, Wproj, 1, nullptr, nullptr, nullptr,
                                            bproj, out);
}